// round 2
// baseline (speedup 1.0000x reference)
#include <cuda_runtime.h>

// Potts energy: out[b] = sum_{i<=j} W[i,j] * [(1-v_bi)(1-v_bj) + v_bi*v_bj]
// Refactor per column j:
//   contrib = cs_j*(1-v_bj) + s1*(2*v_bj-1),  s1 = sum_i Wmask[i,j]*v_bi,
//   cs_j = sum_i Wmask[i,j]  (batch independent)
// => masked GEMM-like: 128 x 1024 x 1024 MACs, tiled 64x64 over upper triangle.

#define Bb   128
#define Nn   1024
#define T    64
#define NT   16          // Nn / T
#define NTILES 136       // NT*(NT+1)/2
#define WTS  68          // Wt row stride (pad, mult of 4 for float4)
#define VIS  129         // V tile row stride (pad for conflict-free stores)

__global__ void zero_out_k(float* out) {
    if (threadIdx.x < Bb) out[threadIdx.x] = 0.0f;
}

extern __shared__ float smem[];

__global__ void __launch_bounds__(256, 1)
potts_tile_k(const float* __restrict__ V,   // [128,1024]
             const float* __restrict__ W,   // [1024,1024]
             float* __restrict__ out)       // [128]
{
    float* Wt = smem;                 // [T][WTS]  Wt[j*WTS + i]  (transposed, masked)
    float* Vi = Wt + T * WTS;         // [T][VIS]  Vi[i*VIS + b]
    float* Vj = Vi + T * VIS;         // [T][VIS]  Vj[j*VIS + b]
    float* cs = Vj + T * VIS;         // [T]

    const int tid = threadIdx.x;

    // map blockIdx.x -> upper-triangular tile (bi, bj), bj >= bi
    int k = blockIdx.x;
    int bi = 0;
    while (k >= NT - bi) { k -= NT - bi; bi++; }
    const int bj  = bi + k;
    const int gi0 = bi * T;
    const int gj0 = bj * T;
    const bool diag = (bi == bj);

    // ---- stage W tile: transpose + triu mask ----
    #pragma unroll
    for (int it = 0; it < 4; it++) {
        int idx = it * 256 + tid;          // 1024 float4 loads
        int ii  = idx >> 4;                // row within tile
        int q   = idx & 15;                // float4 index along j
        float4 w = *(const float4*)(W + (size_t)(gi0 + ii) * Nn + gj0 + q * 4);
        int j0 = q * 4;
        if (diag) {
            if (ii > j0 + 0) w.x = 0.0f;
            if (ii > j0 + 1) w.y = 0.0f;
            if (ii > j0 + 2) w.z = 0.0f;
            if (ii > j0 + 3) w.w = 0.0f;
        }
        Wt[(j0 + 0) * WTS + ii] = w.x;
        Wt[(j0 + 1) * WTS + ii] = w.y;
        Wt[(j0 + 2) * WTS + ii] = w.z;
        Wt[(j0 + 3) * WTS + ii] = w.w;
    }

    // ---- stage V slices, transposed to [n][b] ----
    #pragma unroll
    for (int it = 0; it < 8; it++) {
        int idx = it * 256 + tid;          // 2048 float4 loads per slice
        int b   = idx >> 4;
        int q   = idx & 15;
        float4 a = *(const float4*)(V + (size_t)b * Nn + gi0 + q * 4);
        Vi[(q * 4 + 0) * VIS + b] = a.x;
        Vi[(q * 4 + 1) * VIS + b] = a.y;
        Vi[(q * 4 + 2) * VIS + b] = a.z;
        Vi[(q * 4 + 3) * VIS + b] = a.w;
        float4 c = *(const float4*)(V + (size_t)b * Nn + gj0 + q * 4);
        Vj[(q * 4 + 0) * VIS + b] = c.x;
        Vj[(q * 4 + 1) * VIS + b] = c.y;
        Vj[(q * 4 + 2) * VIS + b] = c.z;
        Vj[(q * 4 + 3) * VIS + b] = c.w;
    }
    __syncthreads();

    // ---- column sums of masked tile (batch-independent) ----
    if (tid < T) {
        float s = 0.0f;
        #pragma unroll
        for (int i = 0; i < T; i++) s += Wt[tid * WTS + i];
        cs[tid] = s;
    }
    __syncthreads();

    // ---- main compute: thread = (batch b, j-half h) ----
    const int b = tid & 127;
    const int h = tid >> 7;                // 0 or 1 -> 32 columns each

    float vi[T];
    #pragma unroll
    for (int i = 0; i < T; i++) vi[i] = Vi[i * VIS + b];

    float acc = 0.0f;
    for (int jj = 0; jj < 32; jj++) {
        const int j = h * 32 + jj;
        const float4* wr = (const float4*)(Wt + j * WTS);
        float s1a = 0.0f, s1b = 0.0f;
        #pragma unroll
        for (int i4 = 0; i4 < 16; i4++) {
            float4 w = wr[i4];
            s1a += w.x * vi[4 * i4 + 0];
            s1b += w.y * vi[4 * i4 + 1];
            s1a += w.z * vi[4 * i4 + 2];
            s1b += w.w * vi[4 * i4 + 3];
        }
        const float s1  = s1a + s1b;
        const float vbj = Vj[j * VIS + b];
        acc += cs[j] * (1.0f - vbj) + s1 * (2.0f * vbj - 1.0f);
    }

    atomicAdd(&out[b], acc);
}

extern "C" void kernel_launch(void* const* d_in, const int* in_sizes, int n_in,
                              void* d_out, int out_size)
{
    const float* V = (const float*)d_in[0];   // vector [128,1024]
    const float* W = (const float*)d_in[1];   // interactions [1024,1024]
    float* out = (float*)d_out;               // [128] fp32

    const int smem_bytes = (T * WTS + 2 * T * VIS + T) * (int)sizeof(float); // 83712
    cudaFuncSetAttribute(potts_tile_k, cudaFuncAttributeMaxDynamicSharedMemorySize,
                         smem_bytes);

    zero_out_k<<<1, 128>>>(out);
    potts_tile_k<<<NTILES, 256, smem_bytes>>>(V, W, out);
}